// round 14
// baseline (speedup 1.0000x reference)
#include <cuda_runtime.h>
#include <cuda_fp16.h>
#include <math.h>

#define NN 8
#define C_IN 64
#define C_OUT 64
#define HH 128
#define WW 128
#define KK 4

typedef unsigned int u32;

// ---------------- scratch (device globals; no allocations allowed) ----------
__device__ float g_sums[NN][45];                 // zero at load; re-zeroed by conv kernel
__device__ __half g_wh[NN * 9 * C_OUT * C_IN];   // fused weight fp16, [n][tap][co][ci]

// ---------------- kernel 1: 45 class sums (eighth-channel warps, float4) ----
__global__ void class_sums_kernel(const float* __restrict__ x) {
    int gwarp = (blockIdx.x * blockDim.x + threadIdx.x) >> 5;   // 0..4095
    int lane = threadIdx.x & 31;
    int ch = gwarp >> 3, q = gwarp & 7;          // 8 slices of 16 rows
    int n = ch >> 6, c = ch & 63;
    const float* p = x + (size_t)(n * C_IN + c) * (HH * WW);
    const float4* pr4 = (const float4*)(p + q * 16 * WW);

    float T = 0.f;
    #pragma unroll 8
    for (int i = lane; i < 16 * WW / 4; i += 32) {
        float4 v = pr4[i];
        T += (v.x + v.y) + (v.z + v.w);
    }
    float R0 = 0.f, RL = 0.f;
    if (q == 0) {
        float4 v = ((const float4*)p)[lane];
        R0 = (v.x + v.y) + (v.z + v.w);
    }
    if (q == 7) {
        float4 v = ((const float4*)(p + (HH - 1) * WW))[lane];
        RL = (v.x + v.y) + (v.z + v.w);
    }
    float C0 = 0.f, CL = 0.f;
    if (lane < 16) {
        int h = q * 16 + lane;
        C0 = p[h * WW];
        CL = p[h * WW + WW - 1];
    }

    #pragma unroll
    for (int o = 16; o; o >>= 1) {
        T  += __shfl_xor_sync(0xffffffffu, T, o);
        R0 += __shfl_xor_sync(0xffffffffu, R0, o);
        RL += __shfl_xor_sync(0xffffffffu, RL, o);
        C0 += __shfl_xor_sync(0xffffffffu, C0, o);
        CL += __shfl_xor_sync(0xffffffffu, CL, o);
    }
    float c00 = (q == 0) ? p[0] : 0.f;
    float c0L = (q == 0) ? p[WW - 1] : 0.f;
    float cL0 = (q == 7) ? p[(HH - 1) * WW] : 0.f;
    float cLL = (q == 7) ? p[HH * WW - 1] : 0.f;
    float S[9];
    S[0] = c00;  S[2] = c0L;
    S[1] = R0 - c00 - c0L;
    S[6] = cL0;  S[8] = cLL;
    S[7] = RL - cL0 - cLL;
    S[3] = C0 - c00 - cL0;
    S[5] = CL - c0L - cLL;
    S[4] = T - R0 - RL - S[3] - S[5];
    int cd = (c == 0) ? 0 : (c == 1) ? 1 : (c == C_IN - 2) ? 3 : (c == C_IN - 1) ? 4 : 2;
    if (lane < 9) atomicAdd(&g_sums[n][cd * 9 + lane], S[lane]);
}

// ---------------- kernel 2: logits+softmax (inline) + fused weight -> fp16 --
__global__ __launch_bounds__(256)
void agg_weights_kernel(const float* __restrict__ weight,
                        const float* __restrict__ conv_w,
                        const float* __restrict__ net0_w,
                        const float* __restrict__ net0_b,
                        const float* __restrict__ net1_w,
                        const float* __restrict__ net1_b,
                        const float* __restrict__ net2_w,
                        const float* __restrict__ net2_b) {
    __shared__ float s[8 * 576];
    __shared__ float lg_s[KK];
    __shared__ float att_s[KK];
    int n = blockIdx.x >> 3;
    int cob = blockIdx.x & 7;                    // block of 8 co
    int tid = threadIdx.x;

    if (tid < KK) {
        int k = tid;
        float S[5][3][3];
        #pragma unroll
        for (int i = 0; i < 45; i++) ((float*)S)[i] = g_sums[n][i];
        float Stot = 0.f;
        #pragma unroll
        for (int i = 0; i < 45; i++) Stot += ((float*)S)[i];

        const float mh[3][3]  = {{0,1,1},{1,1,1},{1,1,0}};
        const float m1d[3][5] = {{0,1,1,1,1},{1,1,1,1,1},{1,1,1,1,0}};
        const float m2d[5][5] = {{0,0,1,1,1},{0,1,1,1,1},{1,1,1,1,1},{1,1,1,1,0},{1,1,1,0,0}};
        const float invV = 1.0f / (float)(C_IN * HH * WW);

        float acc = net0_b[k] + net1_b[k] + net2_b[k] + net0_w[k] * Stot * invV;

        float s1 = 0.f;
        for (int td = 0; td < 3; td++) {
            float B[3][3];
            for (int chh = 0; chh < 3; chh++)
                for (int cw = 0; cw < 3; cw++) {
                    float v = 0.f;
                    for (int cd = 0; cd < 5; cd++) v += m1d[td][cd] * S[cd][chh][cw];
                    B[chh][cw] = v;
                }
            for (int th = 0; th < 3; th++)
                for (int tw = 0; tw < 3; tw++) {
                    float box = 0.f;
                    for (int chh = 0; chh < 3; chh++)
                        for (int cw = 0; cw < 3; cw++)
                            box += mh[th][chh] * mh[tw][cw] * B[chh][cw];
                    s1 += net1_w[k * 27 + td * 9 + th * 3 + tw] * box;
                }
        }
        float s2 = 0.f;
        for (int td = 0; td < 5; td++) {
            float B[3][3];
            for (int chh = 0; chh < 3; chh++)
                for (int cw = 0; cw < 3; cw++) {
                    float v = 0.f;
                    for (int cd = 0; cd < 5; cd++) v += m2d[td][cd] * S[cd][chh][cw];
                    B[chh][cw] = v;
                }
            for (int th = 0; th < 3; th++)
                for (int tw = 0; tw < 3; tw++) {
                    float box = 0.f;
                    for (int chh = 0; chh < 3; chh++)
                        for (int cw = 0; cw < 3; cw++)
                            box += mh[th][chh] * mh[tw][cw] * B[chh][cw];
                    s2 += net2_w[k * 45 + td * 9 + th * 3 + tw] * box;
                }
        }
        lg_s[k] = acc + (s1 + s2) * invV;
    }
    __syncthreads();
    if (tid < KK) {
        float m = lg_s[0];
        #pragma unroll
        for (int j = 1; j < KK; j++) m = fmaxf(m, lg_s[j]);
        float sum = 0.f;
        #pragma unroll
        for (int j = 0; j < KK; j++) sum += expf(lg_s[j] - m);
        att_s[tid] = expf(lg_s[tid] - m) / sum;
    }
    __syncthreads();

    float a0 = att_s[0], a1 = att_s[1], a2 = att_s[2], a3 = att_s[3];
    const int PER_K = C_OUT * C_IN * 9;
    int base = cob * 8 * 576;
    #pragma unroll
    for (int i = tid; i < 4608; i += 256) {
        float v = conv_w[base + i]
                + a0 * weight[0 * PER_K + base + i]
                + a1 * weight[1 * PER_K + base + i]
                + a2 * weight[2 * PER_K + base + i]
                + a3 * weight[3 * PER_K + base + i];
        s[i] = v;
    }
    __syncthreads();
    #pragma unroll
    for (int i = tid; i < 4608; i += 256) {
        int t = i / 512;
        int r = i - t * 512;
        int j = r >> 6, ci = r & 63;
        g_wh[(((size_t)n * 9 + t) * C_OUT + cob * 8 + j) * C_IN + ci] =
            __float2half_rn(s[(j * 64 + ci) * 9 + t]);
    }
}

// ---------------- kernel 3: tensor-core implicit-GEMM conv ------------------
__device__ __forceinline__ u32 su32(const void* p) {
    return (u32)__cvta_generic_to_shared(p);
}

#define LDSM4(R, ADDR)                                                         \
    asm volatile("ldmatrix.sync.aligned.m8n8.x4.shared.b16 {%0,%1,%2,%3}, [%4];" \
                 : "=r"((R)[0]), "=r"((R)[1]), "=r"((R)[2]), "=r"((R)[3])      \
                 : "r"(ADDR))

#define MMA_FP16(C, A, B0, B1)                                                 \
    asm volatile("mma.sync.aligned.m16n8k16.row.col.f32.f16.f16.f32 "         \
                 "{%0,%1,%2,%3}, {%4,%5,%6,%7}, {%8,%9}, {%0,%1,%2,%3};"      \
                 : "+f"((C)[0]), "+f"((C)[1]), "+f"((C)[2]), "+f"((C)[3])     \
                 : "r"((A)[0]), "r"((A)[1]), "r"((A)[2]), "r"((A)[3]),        \
                   "r"(B0), "r"(B1))

#define CP_ASYNC16(DST, SRC)                                                   \
    asm volatile("cp.async.cg.shared.global [%0], [%1], 16;" :: "r"(DST), "l"(SRC))
#define CP_ASYNC_WAIT()                                                        \
    asm volatile("cp.async.commit_group;\ncp.async.wait_group 0;" ::: "memory")

// Block: 256 threads (8 warps). Tile 16h x 16w x 64co; warp = h-pair, N_w=64.
// smem: xh 324 rows (18x18 halo) x 128B swizzled = 41472B
//       Bs  576 rows (9 taps x 64 co) x 128B     = 73728B  (all taps resident)
// total 115200B -> 2 blocks/SM (225KB of 228KB)
#define XS_BYTES (324 * 128)
#define SMEM_BYTES (XS_BYTES + 576 * 128)

__global__ __launch_bounds__(256, 2)
void conv_mma_kernel(const float* __restrict__ x,
                     const float* __restrict__ conv_b,
                     float* __restrict__ out) {
    extern __shared__ char sm[];
    char* xhb = sm;
    char* bsb = sm + XS_BYTES;
    u32 xh_s = su32(xhb), bs_s = su32(bsb);

    int w0 = blockIdx.x * 16, h0 = blockIdx.y * 16, n = blockIdx.z;
    int tid = threadIdx.x, hp = tid >> 5, lane = tid & 31;   // hp = h-pair 0..7

    // designated block restores g_sums = 0 for the next run
    if (blockIdx.x == 0 && blockIdx.y == 0 && blockIdx.z == 0) {
        for (int i = tid; i < NN * 45; i += 256) ((float*)g_sums)[i] = 0.0f;
    }

    // --- B: all 9 taps via cp.async (16B, swizzled) ---------------------------
    const __half* whn = g_wh + (size_t)n * 9 * C_OUT * C_IN;
    #pragma unroll
    for (int i = tid; i < 4608; i += 256) {
        int tap = i >> 9;
        int r = i & 511;
        int co = r >> 3, q = r & 7;
        u32 dst = bs_s + (u32)(tap * C_OUT + co) * 128 + ((q ^ (co & 7)) << 4);
        CP_ASYNC16(dst, whn + ((size_t)(tap * C_OUT + co)) * C_IN + q * 8);
    }

    // --- x tile (18x18 halo): thread per (pos, 8-ci chunk) -> one STS.128 -----
    const float* xn = x + (size_t)n * C_IN * HH * WW;
    for (int i = tid; i < 324 * 8; i += 256) {
        int cib = i / 324;                       // 8-ci chunk index 0..7
        int pos = i - cib * 324;
        int r = pos / 18, c = pos - r * 18;
        int gh = h0 - 1 + r, gw = w0 - 1 + c;
        bool valid = (unsigned)gh < (unsigned)HH && (unsigned)gw < (unsigned)WW;
        const float* px = xn + (size_t)cib * 8 * (HH * WW) + gh * WW + gw;
        u32 pk[4];
        #pragma unroll
        for (int j = 0; j < 4; j++) {
            float v0 = valid ? px[(2 * j + 0) * (HH * WW)] : 0.f;
            float v1 = valid ? px[(2 * j + 1) * (HH * WW)] : 0.f;
            __half2 h2 = __floats2half2_rn(v0, v1);
            pk[j] = *(u32*)&h2;
        }
        u32 off = (u32)pos * 128 + ((cib ^ (pos & 7)) << 4);
        asm volatile("st.shared.v4.b32 [%0], {%1,%2,%3,%4};"
                     :: "r"(xh_s + off), "r"(pk[0]), "r"(pk[1]), "r"(pk[2]), "r"(pk[3]));
    }
    CP_ASYNC_WAIT();
    __syncthreads();

    float acc[2][8][4];
    #pragma unroll
    for (int mf = 0; mf < 2; mf++)
        #pragma unroll
        for (int nf = 0; nf < 8; nf++)
            #pragma unroll
            for (int r = 0; r < 4; r++) acc[mf][nf][r] = 0.f;

    // ldmatrix lane geometry (validated mapping)
    int arow = lane & 15;                        // A: w_local row
    int acb  = lane >> 4;                        // A: k chunk (0/1)
    int brow = (lane & 7) + ((lane >> 4) << 3);  // B: co row within 16
    int bcb  = (lane >> 3) & 1;                  // B: k chunk (0/1)
    int br7  = brow & 7;

    // --- barrier-free main loop: 9 taps x 4 kc --------------------------------
    #pragma unroll
    for (int g = 0; g < 3; g++) {                // kh
        #pragma unroll
        for (int tl = 0; tl < 3; tl++) {         // kw
            int rowA0 = (2 * hp + g) * 18 + arow + tl;
            int rowA1 = rowA0 + 18;
            u32 rbA0 = (u32)rowA0 * 128, rA0_7 = rowA0 & 7;
            u32 rbA1 = (u32)rowA1 * 128, rA1_7 = rowA1 & 7;
            u32 tapbase = (u32)((g * 3 + tl) * C_OUT);
            #pragma unroll
            for (int kc = 0; kc < 4; kc++) {
                int chA = acb + 2 * kc;
                u32 a0 = rbA0 + (u32)((chA ^ rA0_7) << 4);
                u32 a1 = rbA1 + (u32)((chA ^ rA1_7) << 4);
                u32 ah0[4], ah1[4];
                LDSM4(ah0, xh_s + a0);
                LDSM4(ah1, xh_s + a1);
                u32 bh[16];
                u32 cB = (u32)(((bcb + 2 * kc) ^ br7) << 4);
                #pragma unroll
                for (int p = 0; p < 4; p++) {
                    u32 rowB = (tapbase + brow + p * 16) * 128;
                    LDSM4(&bh[4 * p], bs_s + rowB + cB);
                }
                #pragma unroll
                for (int nf = 0; nf < 8; nf++) {
                    int bi = (nf >> 1) * 4 + (nf & 1) * 2;
                    MMA_FP16(acc[0][nf], ah0, bh[bi], bh[bi + 1]);
                    MMA_FP16(acc[1][nf], ah1, bh[bi], bh[bi + 1]);
                }
            }
        }
    }

    // --- epilogue: add bias, store --------------------------------------------
    int gg = lane >> 2, tig = lane & 3;
    #pragma unroll
    for (int mf = 0; mf < 2; mf++) {
        int h = h0 + 2 * hp + mf;
        #pragma unroll
        for (int nf = 0; nf < 8; nf++) {
            int co = nf * 8 + tig * 2;
            float b0 = conv_b[co], b1 = conv_b[co + 1];
            size_t base = ((size_t)(n * C_OUT + co) * HH + h) * WW + w0;
            out[base + gg]                 = acc[mf][nf][0] + b0;
            out[base + HH * WW + gg]       = acc[mf][nf][1] + b1;
            out[base + gg + 8]             = acc[mf][nf][2] + b0;
            out[base + HH * WW + gg + 8]   = acc[mf][nf][3] + b1;
        }
    }
}

// ---------------- launch -----------------------------------------------------
extern "C" void kernel_launch(void* const* d_in, const int* in_sizes, int n_in,
                              void* d_out, int out_size) {
    const float* x      = (const float*)d_in[0];
    const float* weight = (const float*)d_in[1];
    const float* conv_w = (const float*)d_in[2];
    const float* conv_b = (const float*)d_in[3];
    const float* net0_w = (const float*)d_in[4];
    const float* net0_b = (const float*)d_in[5];
    const float* net1_w = (const float*)d_in[6];
    const float* net1_b = (const float*)d_in[7];
    const float* net2_w = (const float*)d_in[8];
    const float* net2_b = (const float*)d_in[9];
    float* out = (float*)d_out;

    static int smem_set = 0;
    if (!smem_set) {
        cudaFuncSetAttribute(conv_mma_kernel,
                             cudaFuncAttributeMaxDynamicSharedMemorySize, SMEM_BYTES);
        smem_set = 1;
    }

    class_sums_kernel<<<512, 256>>>(x);
    agg_weights_kernel<<<NN * 8, 256>>>(weight, conv_w, net0_w, net0_b,
                                        net1_w, net1_b, net2_w, net2_b);
    conv_mma_kernel<<<dim3(WW / 16, HH / 16, NN), 256, SMEM_BYTES>>>(x, conv_b, out);
}

// round 15
// speedup vs baseline: 1.2543x; 1.2543x over previous
#include <cuda_runtime.h>
#include <cuda_fp16.h>
#include <math.h>

#define NN 8
#define C_IN 64
#define C_OUT 64
#define HH 128
#define WW 128
#define KK 4

typedef unsigned int u32;

// ---------------- scratch (device globals; no allocations allowed) ----------
__device__ float g_sums[NN][45];                 // zero at load; re-zeroed by conv kernel
__device__ __half g_wh[NN * 9 * C_OUT * C_IN];   // fused weight fp16, [n][tap][co][ci]

// ---------------- kernel 1: 45 class sums (block = one channel) -------------
// 8 warps/block = 8 slices of 16 rows; block-level smem reduction, then ONE
// set of 9 atomics per channel (cuts atomic traffic 8x vs per-warp atomics).
__global__ __launch_bounds__(256)
void class_sums_kernel(const float* __restrict__ x) {
    __shared__ float part[8][5];
    __shared__ float Ssh[9];
    int b = blockIdx.x;                          // 0..511
    int n = b >> 6, c = b & 63;
    int tid = threadIdx.x, q = tid >> 5, lane = tid & 31;
    const float* p = x + (size_t)(n * C_IN + c) * (HH * WW);
    const float4* pr4 = (const float4*)(p + q * 16 * WW);

    float T = 0.f;
    #pragma unroll 8
    for (int i = lane; i < 16 * WW / 4; i += 32) {
        float4 v = pr4[i];
        T += (v.x + v.y) + (v.z + v.w);
    }
    float R0 = 0.f, RL = 0.f;
    if (q == 0) {
        float4 v = ((const float4*)p)[lane];
        R0 = (v.x + v.y) + (v.z + v.w);
    }
    if (q == 7) {
        float4 v = ((const float4*)(p + (HH - 1) * WW))[lane];
        RL = (v.x + v.y) + (v.z + v.w);
    }
    float C0 = 0.f, CL = 0.f;
    if (lane < 16) {
        int h = q * 16 + lane;
        C0 = p[h * WW];
        CL = p[h * WW + WW - 1];
    }

    #pragma unroll
    for (int o = 16; o; o >>= 1) {
        T  += __shfl_xor_sync(0xffffffffu, T, o);
        R0 += __shfl_xor_sync(0xffffffffu, R0, o);
        RL += __shfl_xor_sync(0xffffffffu, RL, o);
        C0 += __shfl_xor_sync(0xffffffffu, C0, o);
        CL += __shfl_xor_sync(0xffffffffu, CL, o);
    }
    if (lane == 0) {
        part[q][0] = T;
        part[q][1] = R0;
        part[q][2] = RL;
        part[q][3] = C0;
        part[q][4] = CL;
    }
    __syncthreads();

    if (tid == 0) {
        float t = 0.f, r0 = 0.f, rl = 0.f, c0 = 0.f, cl = 0.f;
        #pragma unroll
        for (int w = 0; w < 8; w++) {
            t  += part[w][0];
            r0 += part[w][1];
            rl += part[w][2];
            c0 += part[w][3];
            cl += part[w][4];
        }
        float c00 = p[0];
        float c0L = p[WW - 1];
        float cL0 = p[(HH - 1) * WW];
        float cLL = p[HH * WW - 1];
        Ssh[0] = c00;  Ssh[2] = c0L;
        Ssh[1] = r0 - c00 - c0L;
        Ssh[6] = cL0;  Ssh[8] = cLL;
        Ssh[7] = rl - cL0 - cLL;
        Ssh[3] = c0 - c00 - cL0;
        Ssh[5] = cl - c0L - cLL;
        Ssh[4] = t - r0 - rl - Ssh[3] - Ssh[5];
    }
    __syncthreads();
    if (tid < 9) {
        int cd = (c == 0) ? 0 : (c == 1) ? 1 : (c == C_IN - 2) ? 3 : (c == C_IN - 1) ? 4 : 2;
        atomicAdd(&g_sums[n][cd * 9 + tid], Ssh[tid]);
    }
}

// ---------------- kernel 2: logits+softmax (inline) + fused weight -> fp16 --
__global__ __launch_bounds__(256)
void agg_weights_kernel(const float* __restrict__ weight,
                        const float* __restrict__ conv_w,
                        const float* __restrict__ net0_w,
                        const float* __restrict__ net0_b,
                        const float* __restrict__ net1_w,
                        const float* __restrict__ net1_b,
                        const float* __restrict__ net2_w,
                        const float* __restrict__ net2_b) {
    __shared__ float s[8 * 576];
    __shared__ float lg_s[KK];
    __shared__ float att_s[KK];
    int n = blockIdx.x >> 3;
    int cob = blockIdx.x & 7;                    // block of 8 co
    int tid = threadIdx.x;

    if (tid < KK) {
        int k = tid;
        float S[5][3][3];
        #pragma unroll
        for (int i = 0; i < 45; i++) ((float*)S)[i] = g_sums[n][i];
        float Stot = 0.f;
        #pragma unroll
        for (int i = 0; i < 45; i++) Stot += ((float*)S)[i];

        const float mh[3][3]  = {{0,1,1},{1,1,1},{1,1,0}};
        const float m1d[3][5] = {{0,1,1,1,1},{1,1,1,1,1},{1,1,1,1,0}};
        const float m2d[5][5] = {{0,0,1,1,1},{0,1,1,1,1},{1,1,1,1,1},{1,1,1,1,0},{1,1,1,0,0}};
        const float invV = 1.0f / (float)(C_IN * HH * WW);

        float acc = net0_b[k] + net1_b[k] + net2_b[k] + net0_w[k] * Stot * invV;

        float s1 = 0.f;
        for (int td = 0; td < 3; td++) {
            float B[3][3];
            for (int chh = 0; chh < 3; chh++)
                for (int cw = 0; cw < 3; cw++) {
                    float v = 0.f;
                    for (int cd = 0; cd < 5; cd++) v += m1d[td][cd] * S[cd][chh][cw];
                    B[chh][cw] = v;
                }
            for (int th = 0; th < 3; th++)
                for (int tw = 0; tw < 3; tw++) {
                    float box = 0.f;
                    for (int chh = 0; chh < 3; chh++)
                        for (int cw = 0; cw < 3; cw++)
                            box += mh[th][chh] * mh[tw][cw] * B[chh][cw];
                    s1 += net1_w[k * 27 + td * 9 + th * 3 + tw] * box;
                }
        }
        float s2 = 0.f;
        for (int td = 0; td < 5; td++) {
            float B[3][3];
            for (int chh = 0; chh < 3; chh++)
                for (int cw = 0; cw < 3; cw++) {
                    float v = 0.f;
                    for (int cd = 0; cd < 5; cd++) v += m2d[td][cd] * S[cd][chh][cw];
                    B[chh][cw] = v;
                }
            for (int th = 0; th < 3; th++)
                for (int tw = 0; tw < 3; tw++) {
                    float box = 0.f;
                    for (int chh = 0; chh < 3; chh++)
                        for (int cw = 0; cw < 3; cw++)
                            box += mh[th][chh] * mh[tw][cw] * B[chh][cw];
                    s2 += net2_w[k * 45 + td * 9 + th * 3 + tw] * box;
                }
        }
        lg_s[k] = acc + (s1 + s2) * invV;
    }
    __syncthreads();
    if (tid < KK) {
        float m = lg_s[0];
        #pragma unroll
        for (int j = 1; j < KK; j++) m = fmaxf(m, lg_s[j]);
        float sum = 0.f;
        #pragma unroll
        for (int j = 0; j < KK; j++) sum += expf(lg_s[j] - m);
        att_s[tid] = expf(lg_s[tid] - m) / sum;
    }
    __syncthreads();

    float a0 = att_s[0], a1 = att_s[1], a2 = att_s[2], a3 = att_s[3];
    const int PER_K = C_OUT * C_IN * 9;
    int base = cob * 8 * 576;
    #pragma unroll
    for (int i = tid; i < 4608; i += 256) {
        float v = conv_w[base + i]
                + a0 * weight[0 * PER_K + base + i]
                + a1 * weight[1 * PER_K + base + i]
                + a2 * weight[2 * PER_K + base + i]
                + a3 * weight[3 * PER_K + base + i];
        s[i] = v;
    }
    __syncthreads();
    #pragma unroll
    for (int i = tid; i < 4608; i += 256) {
        int t = i / 512;
        int r = i - t * 512;
        int j = r >> 6, ci = r & 63;
        g_wh[(((size_t)n * 9 + t) * C_OUT + cob * 8 + j) * C_IN + ci] =
            __float2half_rn(s[(j * 64 + ci) * 9 + t]);
    }
}

// ---------------- kernel 3: tensor-core implicit-GEMM conv (R10 config) -----
__device__ __forceinline__ u32 su32(const void* p) {
    return (u32)__cvta_generic_to_shared(p);
}

#define LDSM4(R, ADDR)                                                         \
    asm volatile("ldmatrix.sync.aligned.m8n8.x4.shared.b16 {%0,%1,%2,%3}, [%4];" \
                 : "=r"((R)[0]), "=r"((R)[1]), "=r"((R)[2]), "=r"((R)[3])      \
                 : "r"(ADDR))

#define MMA_FP16(C, A, B0, B1)                                                 \
    asm volatile("mma.sync.aligned.m16n8k16.row.col.f32.f16.f16.f32 "         \
                 "{%0,%1,%2,%3}, {%4,%5,%6,%7}, {%8,%9}, {%0,%1,%2,%3};"      \
                 : "+f"((C)[0]), "+f"((C)[1]), "+f"((C)[2]), "+f"((C)[3])     \
                 : "r"((A)[0]), "r"((A)[1]), "r"((A)[2]), "r"((A)[3]),        \
                   "r"(B0), "r"(B1))

#define CP_ASYNC16(DST, SRC)                                                   \
    asm volatile("cp.async.cg.shared.global [%0], [%1], 16;" :: "r"(DST), "l"(SRC))
#define CP_ASYNC_WAIT()                                                        \
    asm volatile("cp.async.commit_group;\ncp.async.wait_group 0;" ::: "memory")

// Block: 128 threads (4 warps). Tile 8h x 16w x 64co; warp = h-pair, N_w=64.
// smem: xh 180 rows (10x18 halo) x 128B swizzled = 23040B
//       Bs  576 rows (9 taps x 64 co) x 128B     = 73728B  (all taps resident)
#define XS_BYTES (180 * 128)
#define SMEM_BYTES (XS_BYTES + 576 * 128)

__global__ __launch_bounds__(128, 2)
void conv_mma_kernel(const float* __restrict__ x,
                     const float* __restrict__ conv_b,
                     float* __restrict__ out) {
    extern __shared__ char sm[];
    char* xhb = sm;
    char* bsb = sm + XS_BYTES;
    u32 xh_s = su32(xhb), bs_s = su32(bsb);

    int w0 = blockIdx.x * 16, h0 = blockIdx.y * 8, n = blockIdx.z;
    int tid = threadIdx.x, hp = tid >> 5, lane = tid & 31;

    // designated block restores g_sums = 0 for the next run
    if (blockIdx.x == 0 && blockIdx.y == 0 && blockIdx.z == 0) {
        for (int i = tid; i < NN * 45; i += 128) ((float*)g_sums)[i] = 0.0f;
    }

    // --- B: all 9 taps via cp.async (16B, swizzled) ---------------------------
    const __half* whn = g_wh + (size_t)n * 9 * C_OUT * C_IN;
    #pragma unroll
    for (int i = tid; i < 4608; i += 128) {
        int tap = i >> 9;
        int r = i & 511;
        int co = r >> 3, q = r & 7;
        u32 dst = bs_s + (u32)(tap * C_OUT + co) * 128 + ((q ^ (co & 7)) << 4);
        CP_ASYNC16(dst, whn + ((size_t)(tap * C_OUT + co)) * C_IN + q * 8);
    }

    // --- x tile: thread per (pos, 8-ci chunk) -> one STS.128 ------------------
    const float* xn = x + (size_t)n * C_IN * HH * WW;
    #pragma unroll
    for (int i = tid; i < 180 * 8; i += 128) {
        int cib = i / 180;                       // 8-ci chunk index 0..7
        int pos = i - cib * 180;
        int r = pos / 18, c = pos - r * 18;
        int gh = h0 - 1 + r, gw = w0 - 1 + c;
        bool valid = (unsigned)gh < (unsigned)HH && (unsigned)gw < (unsigned)WW;
        const float* px = xn + (size_t)cib * 8 * (HH * WW) + gh * WW + gw;
        u32 pk[4];
        #pragma unroll
        for (int j = 0; j < 4; j++) {
            float v0 = valid ? px[(2 * j + 0) * (HH * WW)] : 0.f;
            float v1 = valid ? px[(2 * j + 1) * (HH * WW)] : 0.f;
            __half2 h2 = __floats2half2_rn(v0, v1);
            pk[j] = *(u32*)&h2;
        }
        u32 off = (u32)pos * 128 + ((cib ^ (pos & 7)) << 4);
        asm volatile("st.shared.v4.b32 [%0], {%1,%2,%3,%4};"
                     :: "r"(xh_s + off), "r"(pk[0]), "r"(pk[1]), "r"(pk[2]), "r"(pk[3]));
    }
    CP_ASYNC_WAIT();
    __syncthreads();

    float acc[2][8][4];
    #pragma unroll
    for (int mf = 0; mf < 2; mf++)
        #pragma unroll
        for (int nf = 0; nf < 8; nf++)
            #pragma unroll
            for (int r = 0; r < 4; r++) acc[mf][nf][r] = 0.f;

    // ldmatrix lane geometry (validated mapping)
    int arow = lane & 15;                        // A: w_local row
    int acb  = lane >> 4;                        // A: k chunk (0/1)
    int brow = (lane & 7) + ((lane >> 4) << 3);  // B: co row within 16
    int bcb  = (lane >> 3) & 1;                  // B: k chunk (0/1)
    int br7  = brow & 7;

    // --- barrier-free main loop: 9 taps x 4 kc --------------------------------
    #pragma unroll
    for (int g = 0; g < 3; g++) {                // kh
        #pragma unroll
        for (int tl = 0; tl < 3; tl++) {         // kw
            int rowA0 = (2 * hp + g) * 18 + arow + tl;
            int rowA1 = rowA0 + 18;
            u32 rbA0 = (u32)rowA0 * 128, rA0_7 = rowA0 & 7;
            u32 rbA1 = (u32)rowA1 * 128, rA1_7 = rowA1 & 7;
            u32 tapbase = (u32)((g * 3 + tl) * C_OUT);
            #pragma unroll
            for (int kc = 0; kc < 4; kc++) {
                int chA = acb + 2 * kc;
                u32 a0 = rbA0 + (u32)((chA ^ rA0_7) << 4);
                u32 a1 = rbA1 + (u32)((chA ^ rA1_7) << 4);
                u32 ah0[4], ah1[4];
                LDSM4(ah0, xh_s + a0);
                LDSM4(ah1, xh_s + a1);
                u32 bh[16];
                u32 cB = (u32)(((bcb + 2 * kc) ^ br7) << 4);
                #pragma unroll
                for (int p = 0; p < 4; p++) {
                    u32 rowB = (tapbase + brow + p * 16) * 128;
                    LDSM4(&bh[4 * p], bs_s + rowB + cB);
                }
                #pragma unroll
                for (int nf = 0; nf < 8; nf++) {
                    int bi = (nf >> 1) * 4 + (nf & 1) * 2;
                    MMA_FP16(acc[0][nf], ah0, bh[bi], bh[bi + 1]);
                    MMA_FP16(acc[1][nf], ah1, bh[bi], bh[bi + 1]);
                }
            }
        }
    }

    // --- epilogue: add bias, store --------------------------------------------
    int gg = lane >> 2, tig = lane & 3;
    #pragma unroll
    for (int mf = 0; mf < 2; mf++) {
        int h = h0 + 2 * hp + mf;
        #pragma unroll
        for (int nf = 0; nf < 8; nf++) {
            int co = nf * 8 + tig * 2;
            float b0 = conv_b[co], b1 = conv_b[co + 1];
            size_t base = ((size_t)(n * C_OUT + co) * HH + h) * WW + w0;
            out[base + gg]                 = acc[mf][nf][0] + b0;
            out[base + HH * WW + gg]       = acc[mf][nf][1] + b1;
            out[base + gg + 8]             = acc[mf][nf][2] + b0;
            out[base + HH * WW + gg + 8]   = acc[mf][nf][3] + b1;
        }
    }
}

// ---------------- launch -----------------------------------------------------
extern "C" void kernel_launch(void* const* d_in, const int* in_sizes, int n_in,
                              void* d_out, int out_size) {
    const float* x      = (const float*)d_in[0];
    const float* weight = (const float*)d_in[1];
    const float* conv_w = (const float*)d_in[2];
    const float* conv_b = (const float*)d_in[3];
    const float* net0_w = (const float*)d_in[4];
    const float* net0_b = (const float*)d_in[5];
    const float* net1_w = (const float*)d_in[6];
    const float* net1_b = (const float*)d_in[7];
    const float* net2_w = (const float*)d_in[8];
    const float* net2_b = (const float*)d_in[9];
    float* out = (float*)d_out;

    static int smem_set = 0;
    if (!smem_set) {
        cudaFuncSetAttribute(conv_mma_kernel,
                             cudaFuncAttributeMaxDynamicSharedMemorySize, SMEM_BYTES);
        smem_set = 1;
    }

    class_sums_kernel<<<NN * C_IN, 256>>>(x);
    agg_weights_kernel<<<NN * 8, 256>>>(weight, conv_w, net0_w, net0_b,
                                        net1_w, net1_b, net2_w, net2_b);
    conv_mma_kernel<<<dim3(WW / 16, HH / 8, NN), 128, SMEM_BYTES>>>(x, conv_b, out);
}